// round 9
// baseline (speedup 1.0000x reference)
#include <cuda_runtime.h>
#include <cstdint>
#include <cstddef>

// Channel self-attention via Gram restructuring:
//   G_b = X X^T, s_b = X 1
//   E = Wq G Wk^T + (Wq s) bk^T + bq (Wk s)^T + N bq bk^T ; A = softmax(E)
//   M = gamma * Wo (A Wv) ; c = gamma * (Wo A bv + bo)
//   out = M X + c 1^T + X

#define NTOK 36864
#define NCH 128
#define NBAT 8
#define NCHUNK 36
#define CHUNK 1024
#define GW 64     /* gram stage width (cols) */
#define GSTR 68   /* gram smem stride; 68%32==4 -> conflict-free */
#define LDSM 132
#define TOKT 128
#define XST 136   /* X stage stride; 136%32==8 -> conflict-free B frags */

__device__ float g_Gpart[NCHUNK * NBAT * NCH * NCH];
__device__ float g_spart[NCHUNK * NBAT * NCH];
__device__ float g_G[NBAT * NCH * NCH];
__device__ float g_s[NBAT * NCH];
__device__ uint32_t g_Mf[NBAT * 16384];   // M in tf32, mma-fragment-packed (64 KB/batch)
__device__ float g_cvec[NBAT * NCH];

__device__ __forceinline__ uint32_t f2tf32(float f) {
    uint32_t u;
    asm("cvt.rna.tf32.f32 %0, %1;" : "=r"(u) : "f"(f));
    return u;
}

__device__ __forceinline__ void tf32split(float f, uint32_t& hi, uint32_t& lo) {
    uint32_t h;
    asm("cvt.rna.tf32.f32 %0, %1;" : "=r"(h) : "f"(f));
    float fh = __uint_as_float(h);
    float r = f - fh;
    uint32_t l;
    asm("cvt.rna.tf32.f32 %0, %1;" : "=r"(l) : "f"(r));
    hi = h; lo = l;
}

__device__ __forceinline__ void mma8(float* d, const uint32_t* a, uint32_t b0, uint32_t b1) {
    asm volatile(
        "mma.sync.aligned.m16n8k8.row.col.f32.tf32.tf32.f32 "
        "{%0,%1,%2,%3},{%4,%5,%6,%7},{%8,%9},{%0,%1,%2,%3};"
        : "+f"(d[0]), "+f"(d[1]), "+f"(d[2]), "+f"(d[3])
        : "r"(a[0]), "r"(a[1]), "r"(a[2]), "r"(a[3]), "r"(b0), "r"(b1));
}

__device__ __forceinline__ void cpa16(uint32_t dst, const void* src) {
    asm volatile("cp.async.cg.shared.global [%0],[%1],16;" :: "r"(dst), "l"(src));
}

// Fragment-packed M index: element (r, c) of the 128x128 matrix ->
// [kt(16)][mtile(8)][lane(32)][q(4)], lane = 4*grp+tq, q = qhi*2+qlo.
__device__ __forceinline__ int mf_index(int r, int c) {
    int kt = c >> 3, w = c & 7, qhi = w >> 2, tq = w & 3;
    int mtile = r >> 4, rr = r & 15, qlo = rr >> 3, grp = rr & 7;
    return ((kt * 8 + mtile) * 32 + grp * 4 + tq) * 4 + qhi * 2 + qlo;
}

// ---------------------------------------------------------------------------
// Gram: per (chunk, batch) block computes 128x128 partial X X^T over 1024 cols
// (16 stages of 64) plus per-row partial sums. Deterministic. 2 CTAs/SM.
// ---------------------------------------------------------------------------
__global__ __launch_bounds__(256, 2) void k_gram(const float* __restrict__ x) {
    extern __shared__ float sb[];   // 2 x 128 x GSTR = 69632 B
    int b = blockIdx.y, ch = blockIdx.x;
    int t = threadIdx.x;
    int lrow = t >> 1, lcol = (t & 1) << 5;
    int lane = t & 31, wid = t >> 5;
    int grp = lane >> 2, tq = lane & 3;
    int wm = wid & 3, wn = wid >> 2;

    const float* gsrc = x + (size_t)b * NCH * NTOK + (size_t)lrow * NTOK
                          + (size_t)ch * CHUNK + lcol;
    uint32_t sd0 = (uint32_t)__cvta_generic_to_shared(sb + lrow * GSTR + lcol);
    uint32_t sd1 = (uint32_t)__cvta_generic_to_shared(sb + NCH * GSTR + lrow * GSTR + lcol);

    float acc[2][8][4];
    #pragma unroll
    for (int i = 0; i < 2; i++)
        #pragma unroll
        for (int j = 0; j < 8; j++)
            #pragma unroll
            for (int k = 0; k < 4; k++) acc[i][j][k] = 0.f;
    float rsum = 0.f;

    #pragma unroll
    for (int j = 0; j < 8; j++) cpa16(sd0 + j * 16, gsrc + j * 4);
    asm volatile("cp.async.commit_group;");

    const int NST = CHUNK / GW;  // 16
    for (int s = 0; s < NST; s++) {
        if (s + 1 < NST) {
            uint32_t dd = ((s + 1) & 1) ? sd1 : sd0;
            const float* p = gsrc + (s + 1) * GW;
            #pragma unroll
            for (int j = 0; j < 8; j++) cpa16(dd + j * 16, p + j * 4);
            asm volatile("cp.async.commit_group;");
            asm volatile("cp.async.wait_group 1;");
        } else {
            asm volatile("cp.async.wait_group 0;");
        }
        __syncthreads();
        const float* cur = sb + (s & 1) * NCH * GSTR;

        {
            const float4* rp4 = (const float4*)(cur + lrow * GSTR + lcol);
            #pragma unroll
            for (int i = 0; i < 8; i++) {
                float4 v = rp4[i];
                rsum += v.x + v.y + v.z + v.w;
            }
        }

        #pragma unroll
        for (int ks = 0; ks < 8; ks++) {
            int kk = ks * 8;
            uint32_t a[2][4];
            #pragma unroll
            for (int mt = 0; mt < 2; mt++) {
                int r0 = wm * 32 + mt * 16;
                a[mt][0] = f2tf32(cur[(r0 + grp) * GSTR + kk + tq]);
                a[mt][1] = f2tf32(cur[(r0 + grp + 8) * GSTR + kk + tq]);
                a[mt][2] = f2tf32(cur[(r0 + grp) * GSTR + kk + tq + 4]);
                a[mt][3] = f2tf32(cur[(r0 + grp + 8) * GSTR + kk + tq + 4]);
            }
            #pragma unroll
            for (int nt = 0; nt < 8; nt++) {
                int n0 = wn * 64 + nt * 8;
                uint32_t b0 = f2tf32(cur[(n0 + grp) * GSTR + kk + tq]);
                uint32_t b1 = f2tf32(cur[(n0 + grp) * GSTR + kk + tq + 4]);
                mma8(acc[0][nt], a[0], b0, b1);
                mma8(acc[1][nt], a[1], b0, b1);
            }
        }
        __syncthreads();
    }

    float* gp = g_Gpart + ((size_t)ch * NBAT + b) * NCH * NCH;
    #pragma unroll
    for (int mt = 0; mt < 2; mt++) {
        #pragma unroll
        for (int nt = 0; nt < 8; nt++) {
            int r = wm * 32 + mt * 16 + grp;
            int c = wn * 64 + nt * 8 + tq * 2;
            gp[r * NCH + c]           = acc[mt][nt][0];
            gp[r * NCH + c + 1]       = acc[mt][nt][1];
            gp[(r + 8) * NCH + c]     = acc[mt][nt][2];
            gp[(r + 8) * NCH + c + 1] = acc[mt][nt][3];
        }
    }
    rsum += __shfl_xor_sync(0xffffffffu, rsum, 1);
    if ((t & 1) == 0) g_spart[(ch * NBAT + b) * NCH + lrow] = rsum;
}

__global__ void k_gred() {
    int j = blockIdx.x * 256 + threadIdx.x;
    float a = 0.f;
    #pragma unroll
    for (int ch = 0; ch < NCHUNK; ch++) a += g_Gpart[(size_t)ch * (NBAT * NCH * NCH) + j];
    g_G[j] = a;
    if (j < NBAT * NCH) {
        float t2 = 0.f;
        #pragma unroll
        for (int ch = 0; ch < NCHUNK; ch++) t2 += g_spart[ch * (NBAT * NCH) + j];
        g_s[j] = t2;
    }
}

// ---------------------------------------------------------------------------
// Fused small chain: one block per batch, all 128x128 matmuls via MMA in smem.
// ---------------------------------------------------------------------------
template<bool X2, class FA, class FB, class FE>
__device__ __forceinline__ void chain_mm(FA fa, FB fb, FE fe,
                                         int wm, int wn, int grp, int tq) {
    float acc[2][8][4];
    #pragma unroll
    for (int i = 0; i < 2; i++)
        #pragma unroll
        for (int j = 0; j < 8; j++)
            #pragma unroll
            for (int k = 0; k < 4; k++) acc[i][j][k] = 0.f;

    for (int kk = 0; kk < NCH; kk += 8) {
        uint32_t ah[2][4], al[2][4];
        #pragma unroll
        for (int mt = 0; mt < 2; mt++) {
            int r0 = wm * 32 + mt * 16;
            #pragma unroll
            for (int q = 0; q < 4; q++) {
                int rr = r0 + grp + ((q & 1) ? 8 : 0);
                int kc = kk + tq + ((q >> 1) ? 4 : 0);
                float f = fa(rr, kc);
                if constexpr (X2) tf32split(f, ah[mt][q], al[mt][q]);
                else ah[mt][q] = f2tf32(f);
            }
        }
        #pragma unroll
        for (int nt = 0; nt < 8; nt++) {
            int n = wn * 64 + nt * 8 + grp;
            float g0 = fb(n, kk + tq);
            float g1 = fb(n, kk + tq + 4);
            uint32_t bh0, bh1, bl0, bl1;
            if constexpr (X2) { tf32split(g0, bh0, bl0); tf32split(g1, bh1, bl1); }
            else { bh0 = f2tf32(g0); bh1 = f2tf32(g1); }
            mma8(acc[0][nt], ah[0], bh0, bh1);
            mma8(acc[1][nt], ah[1], bh0, bh1);
            if constexpr (X2) {
                mma8(acc[0][nt], al[0], bh0, bh1);
                mma8(acc[1][nt], al[1], bh0, bh1);
                mma8(acc[0][nt], ah[0], bl0, bl1);
                mma8(acc[1][nt], ah[1], bl0, bl1);
            }
        }
    }
    #pragma unroll
    for (int mt = 0; mt < 2; mt++)
        #pragma unroll
        for (int nt = 0; nt < 8; nt++) {
            int r = wm * 32 + mt * 16 + grp;
            int c = wn * 64 + nt * 8 + tq * 2;
            fe(r, c, acc[mt][nt][0], acc[mt][nt][1]);
            fe(r + 8, c, acc[mt][nt][2], acc[mt][nt][3]);
        }
}

__global__ __launch_bounds__(256) void k_chain(
    const float* __restrict__ Wq, const float* __restrict__ bq,
    const float* __restrict__ Wk, const float* __restrict__ bk,
    const float* __restrict__ Wv, const float* __restrict__ bv,
    const float* __restrict__ Wo, const float* __restrict__ bo,
    const float* __restrict__ gamma) {
    extern __shared__ float sm[];
    float* sA = sm;                 // 128 x LDSM
    float* sB = sm + NCH * LDSM;    // 128 x LDSM
    __shared__ float s_s[NCH], s_qs[NCH], s_ks[NCH], s_av[NCH];
    __shared__ float s_bq[NCH], s_bk[NCH], s_bv[NCH];

    int b = blockIdx.x, t = threadIdx.x;
    int lane = t & 31, wid = t >> 5;
    int grp = lane >> 2, tq = lane & 3;
    int wm = wid & 3, wn = wid >> 2;

    if (t < NCH) {
        s_s[t] = g_s[b * NCH + t];
        s_bq[t] = bq[t]; s_bk[t] = bk[t]; s_bv[t] = bv[t];
    }
    __syncthreads();

    // qs = Wq s, ks = Wk s
    {
        int d = t & 127;
        const float* W = (t < NCH) ? Wq : Wk;
        float a = 0.f;
        #pragma unroll 8
        for (int c = 0; c < NCH; c++) a += __ldg(&W[d * NCH + c]) * s_s[c];
        if (t < NCH) s_qs[d] = a; else s_ks[d] = a;
    }

    // G -> sA
    for (int i = t; i < NCH * 32; i += 256) {
        int r = i >> 5, c = (i & 31) << 2;
        *(float4*)(sA + r * LDSM + c) =
            *(const float4*)(g_G + (size_t)b * NCH * NCH + r * NCH + c);
    }
    __syncthreads();

    // T1 = Wq * G -> sB   (tf32x2)
    chain_mm<true>(
        [&](int r, int k) { return __ldg(&Wq[r * NCH + k]); },
        [&](int n, int k) { return sA[k * LDSM + n]; },
        [&](int r, int c, float v0, float v1) {
            sB[r * LDSM + c] = v0; sB[r * LDSM + c + 1] = v1;
        }, wm, wn, grp, tq);
    __syncthreads();

    // E = T1 * Wk^T + rank-1 -> sA   (tf32x2)
    chain_mm<true>(
        [&](int r, int k) { return sB[r * LDSM + k]; },
        [&](int n, int k) { return __ldg(&Wk[n * NCH + k]); },
        [&](int r, int c, float v0, float v1) {
            sA[r * LDSM + c] = v0 + s_qs[r] * s_bk[c]
                             + s_bq[r] * (s_ks[c] + (float)NTOK * s_bk[c]);
            sA[r * LDSM + c + 1] = v1 + s_qs[r] * s_bk[c + 1]
                             + s_bq[r] * (s_ks[c + 1] + (float)NTOK * s_bk[c + 1]);
        }, wm, wn, grp, tq);
    __syncthreads();

    // softmax rows of sA
    for (int r = wid; r < NCH; r += 8) {
        float4 v = *(float4*)(sA + r * LDSM + lane * 4);
        float m = fmaxf(fmaxf(v.x, v.y), fmaxf(v.z, v.w));
        #pragma unroll
        for (int o = 16; o; o >>= 1) m = fmaxf(m, __shfl_xor_sync(0xffffffffu, m, o));
        float e0 = __expf(v.x - m), e1 = __expf(v.y - m);
        float e2 = __expf(v.z - m), e3 = __expf(v.w - m);
        float s2 = e0 + e1 + e2 + e3;
        #pragma unroll
        for (int o = 16; o; o >>= 1) s2 += __shfl_xor_sync(0xffffffffu, s2, o);
        float inv = 1.f / s2;
        v.x = e0 * inv; v.y = e1 * inv; v.z = e2 * inv; v.w = e3 * inv;
        *(float4*)(sA + r * LDSM + lane * 4) = v;
    }
    __syncthreads();

    // av = A * bv
    if (t < NCH) {
        float a = 0.f;
        #pragma unroll 8
        for (int e = 0; e < NCH; e++) a += sA[t * LDSM + e] * s_bv[e];
        s_av[t] = a;
    }
    __syncthreads();

    // U = A * Wv -> sB  (tf32)
    chain_mm<false>(
        [&](int r, int k) { return sA[r * LDSM + k]; },
        [&](int n, int k) { return __ldg(&Wv[k * NCH + n]); },
        [&](int r, int c, float v0, float v1) {
            sB[r * LDSM + c] = v0; sB[r * LDSM + c + 1] = v1;
        }, wm, wn, grp, tq);
    __syncthreads();

    float gmv = __ldg(&gamma[0]);

    // M = gamma * Wo * U -> g_Mf (fragment-packed tf32)
    chain_mm<false>(
        [&](int r, int k) { return __ldg(&Wo[r * NCH + k]); },
        [&](int n, int k) { return sB[k * LDSM + n]; },
        [&](int r, int c, float v0, float v1) {
            g_Mf[b * 16384 + mf_index(r, c)]     = f2tf32(gmv * v0);
            g_Mf[b * 16384 + mf_index(r, c + 1)] = f2tf32(gmv * v1);
        }, wm, wn, grp, tq);

    // cvec = gamma * (Wo av + bo)
    if (t < NCH) {
        float a = 0.f;
        #pragma unroll 8
        for (int h = 0; h < NCH; h++) a += __ldg(&Wo[t * NCH + h]) * s_av[h];
        g_cvec[b * NCH + t] = gmv * (a + bo[t]);
    }
}

// ---------------------------------------------------------------------------
// Output: out = M * X + c 1^T + X
// 128-token tiles, 256 threads, 2 CTAs/SM. FULL 64 KB fragment-packed tf32 M
// staged into smem via cp.async; X double-buffered (2x17 KB). A-frags are one
// conflict-free LDS.128 each. Residual via __ldg (L2 hit - cp.async.cg
// populated L2 with these lines moments earlier).
// ---------------------------------------------------------------------------
__global__ __launch_bounds__(256, 2) void k_out(const float* __restrict__ x,
                                                float* __restrict__ out) {
    extern __shared__ float smem[];
    uint4* sMf = (uint4*)smem;                // 4096 uint4 = 65536 B
    float* sx = smem + 16384;                 // 2 stages x 32 x XST = 34816 B

    int b = blockIdx.y;
    int tok0 = blockIdx.x * TOKT;
    int t = threadIdx.x;
    int lane = t & 31, wid = t >> 5;
    int grp = lane >> 2, tq = lane & 3;
    int wm = wid & 3, wn = wid >> 2;   // wn in {0,1}

    const float* xb = x + (size_t)b * NCH * NTOK;

    int lrow = t >> 3, loff = (t & 7) << 4;   // 32 rows x 128 floats per stage
    const float* gsrc = xb + (size_t)lrow * NTOK + tok0 + loff;
    uint32_t sd0 = (uint32_t)__cvta_generic_to_shared(sx + lrow * XST + loff);
    uint32_t sd1 = (uint32_t)__cvta_generic_to_shared(sx + 32 * XST + lrow * XST + loff);

    // G0: X stage 0 (DRAM - issue first)
    #pragma unroll
    for (int j = 0; j < 4; j++) cpa16(sd0 + j * 16, gsrc + j * 4);
    asm volatile("cp.async.commit_group;");

    // G1: full M fragments (64 KB, L2-resident; 16 uint4 per thread, coalesced)
    {
        const uint4* Mf = (const uint4*)g_Mf + (size_t)b * 4096;
        #pragma unroll
        for (int j = 0; j < 16; j++) {
            int idx = t + j * 256;
            uint32_t sd = (uint32_t)__cvta_generic_to_shared(sMf + idx);
            cpa16(sd, Mf + idx);
        }
        asm volatile("cp.async.commit_group;");
    }

    float acc[2][8][4];
    #pragma unroll
    for (int i = 0; i < 2; i++)
        #pragma unroll
        for (int j = 0; j < 8; j++)
            #pragma unroll
            for (int k = 0; k < 4; k++) acc[i][j][k] = 0.f;

    #pragma unroll
    for (int s = 0; s < 4; s++) {
        if (s + 1 < 4) {
            // commit X stage s+1 into the other buffer
            uint32_t dd = ((s + 1) & 1) ? sd1 : sd0;
            const float* p = gsrc + (size_t)(s + 1) * 32 * NTOK;
            #pragma unroll
            for (int j = 0; j < 4; j++) cpa16(dd + j * 16, p + j * 4);
            asm volatile("cp.async.commit_group;");
            asm volatile("cp.async.wait_group 1;");   // s==0: G0+G1 (X0+M) done
        } else {
            asm volatile("cp.async.wait_group 0;");
        }
        __syncthreads();
        const float* cur = sx + (s & 1) * 32 * XST;

        #pragma unroll
        for (int ks = 0; ks < 4; ks++) {
            int kk = ks * 8;
            int kt = s * 4 + ks;
            uint4 av0 = sMf[(kt * 8 + wm * 2 + 0) * 32 + lane];
            uint4 av1 = sMf[(kt * 8 + wm * 2 + 1) * 32 + lane];
            uint32_t a0[4] = {av0.x, av0.y, av0.z, av0.w};
            uint32_t a1[4] = {av1.x, av1.y, av1.z, av1.w};
            #pragma unroll
            for (int nt = 0; nt < 8; nt++) {
                int n0 = wn * 64 + nt * 8;
                uint32_t b0 = f2tf32(cur[(kk + tq) * XST + n0 + grp]);
                uint32_t b1 = f2tf32(cur[(kk + tq + 4) * XST + n0 + grp]);
                mma8(acc[0][nt], a0, b0, b1);
                mma8(acc[1][nt], a1, b0, b1);
            }
        }
        __syncthreads();   // consumption done before next overwrite
    }

    float* ob = out + (size_t)b * NCH * NTOK;
    #pragma unroll
    for (int mt = 0; mt < 2; mt++) {
        int r  = wm * 32 + mt * 16 + grp;
        int r1 = r + 8;
        float cv0 = g_cvec[b * NCH + r];
        float cv1 = g_cvec[b * NCH + r1];
        #pragma unroll
        for (int nt = 0; nt < 8; nt++) {
            int c = tok0 + wn * 64 + nt * 8 + tq * 2;
            size_t i0 = (size_t)r * NTOK + c;
            size_t i1 = (size_t)r1 * NTOK + c;
            ob[i0]     = acc[mt][nt][0] + cv0 + __ldg(&xb[i0]);
            ob[i0 + 1] = acc[mt][nt][1] + cv0 + __ldg(&xb[i0 + 1]);
            ob[i1]     = acc[mt][nt][2] + cv1 + __ldg(&xb[i1]);
            ob[i1 + 1] = acc[mt][nt][3] + cv1 + __ldg(&xb[i1 + 1]);
        }
    }
}

extern "C" void kernel_launch(void* const* d_in, const int* in_sizes, int n_in,
                              void* d_out, int out_size) {
    const float* x  = (const float*)d_in[0];
    const float* Wq = (const float*)d_in[1];
    const float* bq = (const float*)d_in[2];
    const float* Wk = (const float*)d_in[3];
    const float* bk = (const float*)d_in[4];
    const float* Wv = (const float*)d_in[5];
    const float* bv = (const float*)d_in[6];
    const float* Wo = (const float*)d_in[7];
    const float* bo = (const float*)d_in[8];
    const float* gm = (const float*)d_in[9];
    float* out = (float*)d_out;

    const int gram_smem  = 2 * NCH * GSTR * (int)sizeof(float);          // 69632
    const int chain_smem = 2 * NCH * LDSM * (int)sizeof(float);          // 135168
    const int out_smem   = 65536 + 2 * 32 * XST * (int)sizeof(float);    // 100352
    cudaFuncSetAttribute(k_gram,  cudaFuncAttributeMaxDynamicSharedMemorySize, gram_smem);
    cudaFuncSetAttribute(k_chain, cudaFuncAttributeMaxDynamicSharedMemorySize, chain_smem);
    cudaFuncSetAttribute(k_out,   cudaFuncAttributeMaxDynamicSharedMemorySize, out_smem);

    k_gram<<<dim3(NCHUNK, NBAT), 256, gram_smem>>>(x);
    k_gred<<<(NBAT * NCH * NCH) / 256, 256>>>();
    k_chain<<<NBAT, 256, chain_smem>>>(Wq, bq, Wk, bk, Wv, bv, Wo, bo, gm);
    k_out<<<dim3(NTOK / TOKT, NBAT), 256, out_smem>>>(x, out);
}

// round 10
// speedup vs baseline: 1.0708x; 1.0708x over previous
#include <cuda_runtime.h>
#include <cstdint>
#include <cstddef>

// Channel self-attention via Gram restructuring:
//   G_b = X X^T, s_b = X 1
//   E = Wq G Wk^T + (Wq s) bk^T + bq (Wk s)^T + N bq bk^T ; A = softmax(E)
//   M = gamma * Wo (A Wv) ; c = gamma * (Wo A bv + bo)
//   out = M X + c 1^T + X

#define NTOK 36864
#define NCH 128
#define NBAT 8
#define NCHUNK 36
#define CHUNK 1024
#define GW 64     /* gram stage width (cols) */
#define GSTR 68   /* gram smem stride; 68%32==4 -> conflict-free */
#define LDSM 132
#define TOKT 128
#define XST 136   /* X stage stride; 136%32==8 -> conflict-free B frags */

__device__ float g_Gpart[NCHUNK * NBAT * NCH * NCH];
__device__ float g_spart[NCHUNK * NBAT * NCH];
__device__ float g_G[NBAT * NCH * NCH];
__device__ float g_s[NBAT * NCH];
__device__ uint32_t g_Mf[NBAT * 16384];   // M in tf32, mma-fragment-packed
__device__ float g_cvec[NBAT * NCH];

__device__ __forceinline__ uint32_t f2tf32(float f) {
    uint32_t u;
    asm("cvt.rna.tf32.f32 %0, %1;" : "=r"(u) : "f"(f));
    return u;
}

__device__ __forceinline__ void tf32split(float f, uint32_t& hi, uint32_t& lo) {
    uint32_t h;
    asm("cvt.rna.tf32.f32 %0, %1;" : "=r"(h) : "f"(f));
    float fh = __uint_as_float(h);
    float r = f - fh;
    uint32_t l;
    asm("cvt.rna.tf32.f32 %0, %1;" : "=r"(l) : "f"(r));
    hi = h; lo = l;
}

__device__ __forceinline__ void mma8(float* d, const uint32_t* a, uint32_t b0, uint32_t b1) {
    asm volatile(
        "mma.sync.aligned.m16n8k8.row.col.f32.tf32.tf32.f32 "
        "{%0,%1,%2,%3},{%4,%5,%6,%7},{%8,%9},{%0,%1,%2,%3};"
        : "+f"(d[0]), "+f"(d[1]), "+f"(d[2]), "+f"(d[3])
        : "r"(a[0]), "r"(a[1]), "r"(a[2]), "r"(a[3]), "r"(b0), "r"(b1));
}

__device__ __forceinline__ void cpa16(uint32_t dst, const void* src) {
    asm volatile("cp.async.cg.shared.global [%0],[%1],16;" :: "r"(dst), "l"(src));
}

// Fragment-packed M index: element (r, c) of the 128x128 matrix ->
// [kt(16)][mtile(8)][lane(32)][q(4)], lane = 4*grp+tq, q = qhi*2+qlo.
__device__ __forceinline__ int mf_index(int r, int c) {
    int kt = c >> 3, w = c & 7, qhi = w >> 2, tq = w & 3;
    int mtile = r >> 4, rr = r & 15, qlo = rr >> 3, grp = rr & 7;
    return ((kt * 8 + mtile) * 32 + grp * 4 + tq) * 4 + qhi * 2 + qlo;
}

// ---------------------------------------------------------------------------
// Gram: per (chunk, batch) block computes 128x128 partial X X^T over 1024 cols
// (16 stages of 64). Triple-buffered cp.async, ONE barrier per stage.
// Deterministic. 2 CTAs/SM.
// ---------------------------------------------------------------------------
__global__ __launch_bounds__(256, 2) void k_gram(const float* __restrict__ x) {
    extern __shared__ float sb[];   // 3 x 128 x GSTR = 104448 B
    int b = blockIdx.y, ch = blockIdx.x;
    int t = threadIdx.x;
    int lrow = t >> 1, lcol = (t & 1) << 5;
    int lane = t & 31, wid = t >> 5;
    int grp = lane >> 2, tq = lane & 3;
    int wm = wid & 3, wn = wid >> 2;

    const float* gsrc = x + (size_t)b * NCH * NTOK + (size_t)lrow * NTOK
                          + (size_t)ch * CHUNK + lcol;
    uint32_t sdb[3];
    #pragma unroll
    for (int i = 0; i < 3; i++)
        sdb[i] = (uint32_t)__cvta_generic_to_shared(sb + i * NCH * GSTR + lrow * GSTR + lcol);

    float acc[2][8][4];
    #pragma unroll
    for (int i = 0; i < 2; i++)
        #pragma unroll
        for (int j = 0; j < 8; j++)
            #pragma unroll
            for (int k = 0; k < 4; k++) acc[i][j][k] = 0.f;
    float rsum = 0.f;

    // prologue: stages 0 and 1
    #pragma unroll
    for (int j = 0; j < 8; j++) cpa16(sdb[0] + j * 16, gsrc + j * 4);
    asm volatile("cp.async.commit_group;");
    #pragma unroll
    for (int j = 0; j < 8; j++) cpa16(sdb[1] + j * 16, gsrc + GW + j * 4);
    asm volatile("cp.async.commit_group;");

    const int NST = CHUNK / GW;  // 16
    for (int s = 0; s < NST; s++) {
        if (s + 1 < NST) asm volatile("cp.async.wait_group 1;");
        else             asm volatile("cp.async.wait_group 0;");
        __syncthreads();   // stage s visible; all warps past stage s-1 compute

        if (s + 2 < NST) {   // safe: barrier above proves buf (s+2)%3 is free
            uint32_t dd = sdb[(s + 2) % 3];
            const float* p = gsrc + (s + 2) * GW;
            #pragma unroll
            for (int j = 0; j < 8; j++) cpa16(dd + j * 16, p + j * 4);
            asm volatile("cp.async.commit_group;");
        }

        const float* cur = sb + (s % 3) * NCH * GSTR;

        {
            const float4* rp4 = (const float4*)(cur + lrow * GSTR + lcol);
            #pragma unroll
            for (int i = 0; i < 8; i++) {
                float4 v = rp4[i];
                rsum += v.x + v.y + v.z + v.w;
            }
        }

        #pragma unroll
        for (int ks = 0; ks < 8; ks++) {
            int kk = ks * 8;
            uint32_t a[2][4];
            #pragma unroll
            for (int mt = 0; mt < 2; mt++) {
                int r0 = wm * 32 + mt * 16;
                a[mt][0] = f2tf32(cur[(r0 + grp) * GSTR + kk + tq]);
                a[mt][1] = f2tf32(cur[(r0 + grp + 8) * GSTR + kk + tq]);
                a[mt][2] = f2tf32(cur[(r0 + grp) * GSTR + kk + tq + 4]);
                a[mt][3] = f2tf32(cur[(r0 + grp + 8) * GSTR + kk + tq + 4]);
            }
            #pragma unroll
            for (int nt = 0; nt < 8; nt++) {
                int n0 = wn * 64 + nt * 8;
                uint32_t b0 = f2tf32(cur[(n0 + grp) * GSTR + kk + tq]);
                uint32_t b1 = f2tf32(cur[(n0 + grp) * GSTR + kk + tq + 4]);
                mma8(acc[0][nt], a[0], b0, b1);
                mma8(acc[1][nt], a[1], b0, b1);
            }
        }
        // no bottom barrier: next stage's top barrier provides the fence
    }

    float* gp = g_Gpart + ((size_t)ch * NBAT + b) * NCH * NCH;
    #pragma unroll
    for (int mt = 0; mt < 2; mt++) {
        #pragma unroll
        for (int nt = 0; nt < 8; nt++) {
            int r = wm * 32 + mt * 16 + grp;
            int c = wn * 64 + nt * 8 + tq * 2;
            gp[r * NCH + c]           = acc[mt][nt][0];
            gp[r * NCH + c + 1]       = acc[mt][nt][1];
            gp[(r + 8) * NCH + c]     = acc[mt][nt][2];
            gp[(r + 8) * NCH + c + 1] = acc[mt][nt][3];
        }
    }
    rsum += __shfl_xor_sync(0xffffffffu, rsum, 1);
    if ((t & 1) == 0) g_spart[(ch * NBAT + b) * NCH + lrow] = rsum;
}

__global__ void k_gred() {
    int j = blockIdx.x * 256 + threadIdx.x;
    float a = 0.f;
    #pragma unroll
    for (int ch = 0; ch < NCHUNK; ch++) a += g_Gpart[(size_t)ch * (NBAT * NCH * NCH) + j];
    g_G[j] = a;
    if (j < NBAT * NCH) {
        float t2 = 0.f;
        #pragma unroll
        for (int ch = 0; ch < NCHUNK; ch++) t2 += g_spart[ch * (NBAT * NCH) + j];
        g_s[j] = t2;
    }
}

// ---------------------------------------------------------------------------
// Fused small chain: one block per batch, all 128x128 matmuls via MMA in smem.
// ---------------------------------------------------------------------------
template<bool X2, class FA, class FB, class FE>
__device__ __forceinline__ void chain_mm(FA fa, FB fb, FE fe,
                                         int wm, int wn, int grp, int tq) {
    float acc[2][8][4];
    #pragma unroll
    for (int i = 0; i < 2; i++)
        #pragma unroll
        for (int j = 0; j < 8; j++)
            #pragma unroll
            for (int k = 0; k < 4; k++) acc[i][j][k] = 0.f;

    for (int kk = 0; kk < NCH; kk += 8) {
        uint32_t ah[2][4], al[2][4];
        #pragma unroll
        for (int mt = 0; mt < 2; mt++) {
            int r0 = wm * 32 + mt * 16;
            #pragma unroll
            for (int q = 0; q < 4; q++) {
                int rr = r0 + grp + ((q & 1) ? 8 : 0);
                int kc = kk + tq + ((q >> 1) ? 4 : 0);
                float f = fa(rr, kc);
                if constexpr (X2) tf32split(f, ah[mt][q], al[mt][q]);
                else ah[mt][q] = f2tf32(f);
            }
        }
        #pragma unroll
        for (int nt = 0; nt < 8; nt++) {
            int n = wn * 64 + nt * 8 + grp;
            float g0 = fb(n, kk + tq);
            float g1 = fb(n, kk + tq + 4);
            uint32_t bh0, bh1, bl0, bl1;
            if constexpr (X2) { tf32split(g0, bh0, bl0); tf32split(g1, bh1, bl1); }
            else { bh0 = f2tf32(g0); bh1 = f2tf32(g1); }
            mma8(acc[0][nt], ah[0], bh0, bh1);
            mma8(acc[1][nt], ah[1], bh0, bh1);
            if constexpr (X2) {
                mma8(acc[0][nt], al[0], bh0, bh1);
                mma8(acc[1][nt], al[1], bh0, bh1);
                mma8(acc[0][nt], ah[0], bl0, bl1);
                mma8(acc[1][nt], ah[1], bl0, bl1);
            }
        }
    }
    #pragma unroll
    for (int mt = 0; mt < 2; mt++)
        #pragma unroll
        for (int nt = 0; nt < 8; nt++) {
            int r = wm * 32 + mt * 16 + grp;
            int c = wn * 64 + nt * 8 + tq * 2;
            fe(r, c, acc[mt][nt][0], acc[mt][nt][1]);
            fe(r + 8, c, acc[mt][nt][2], acc[mt][nt][3]);
        }
}

__global__ __launch_bounds__(256) void k_chain(
    const float* __restrict__ Wq, const float* __restrict__ bq,
    const float* __restrict__ Wk, const float* __restrict__ bk,
    const float* __restrict__ Wv, const float* __restrict__ bv,
    const float* __restrict__ Wo, const float* __restrict__ bo,
    const float* __restrict__ gamma) {
    extern __shared__ float sm[];
    float* sA = sm;                 // 128 x LDSM
    float* sB = sm + NCH * LDSM;    // 128 x LDSM
    __shared__ float s_s[NCH], s_qs[NCH], s_ks[NCH], s_av[NCH];
    __shared__ float s_bq[NCH], s_bk[NCH], s_bv[NCH];

    int b = blockIdx.x, t = threadIdx.x;
    int lane = t & 31, wid = t >> 5;
    int grp = lane >> 2, tq = lane & 3;
    int wm = wid & 3, wn = wid >> 2;

    if (t < NCH) {
        s_s[t] = g_s[b * NCH + t];
        s_bq[t] = bq[t]; s_bk[t] = bk[t]; s_bv[t] = bv[t];
    }
    __syncthreads();

    // qs = Wq s, ks = Wk s
    {
        int d = t & 127;
        const float* W = (t < NCH) ? Wq : Wk;
        float a = 0.f;
        #pragma unroll 8
        for (int c = 0; c < NCH; c++) a += __ldg(&W[d * NCH + c]) * s_s[c];
        if (t < NCH) s_qs[d] = a; else s_ks[d] = a;
    }

    // G -> sA
    for (int i = t; i < NCH * 32; i += 256) {
        int r = i >> 5, c = (i & 31) << 2;
        *(float4*)(sA + r * LDSM + c) =
            *(const float4*)(g_G + (size_t)b * NCH * NCH + r * NCH + c);
    }
    __syncthreads();

    // T1 = Wq * G -> sB   (tf32x2)
    chain_mm<true>(
        [&](int r, int k) { return __ldg(&Wq[r * NCH + k]); },
        [&](int n, int k) { return sA[k * LDSM + n]; },
        [&](int r, int c, float v0, float v1) {
            sB[r * LDSM + c] = v0; sB[r * LDSM + c + 1] = v1;
        }, wm, wn, grp, tq);
    __syncthreads();

    // E = T1 * Wk^T + rank-1 -> sA   (tf32x2)
    chain_mm<true>(
        [&](int r, int k) { return sB[r * LDSM + k]; },
        [&](int n, int k) { return __ldg(&Wk[n * NCH + k]); },
        [&](int r, int c, float v0, float v1) {
            sA[r * LDSM + c] = v0 + s_qs[r] * s_bk[c]
                             + s_bq[r] * (s_ks[c] + (float)NTOK * s_bk[c]);
            sA[r * LDSM + c + 1] = v1 + s_qs[r] * s_bk[c + 1]
                             + s_bq[r] * (s_ks[c + 1] + (float)NTOK * s_bk[c + 1]);
        }, wm, wn, grp, tq);
    __syncthreads();

    // softmax rows of sA
    for (int r = wid; r < NCH; r += 8) {
        float4 v = *(float4*)(sA + r * LDSM + lane * 4);
        float m = fmaxf(fmaxf(v.x, v.y), fmaxf(v.z, v.w));
        #pragma unroll
        for (int o = 16; o; o >>= 1) m = fmaxf(m, __shfl_xor_sync(0xffffffffu, m, o));
        float e0 = __expf(v.x - m), e1 = __expf(v.y - m);
        float e2 = __expf(v.z - m), e3 = __expf(v.w - m);
        float s2 = e0 + e1 + e2 + e3;
        #pragma unroll
        for (int o = 16; o; o >>= 1) s2 += __shfl_xor_sync(0xffffffffu, s2, o);
        float inv = 1.f / s2;
        v.x = e0 * inv; v.y = e1 * inv; v.z = e2 * inv; v.w = e3 * inv;
        *(float4*)(sA + r * LDSM + lane * 4) = v;
    }
    __syncthreads();

    // av = A * bv
    if (t < NCH) {
        float a = 0.f;
        #pragma unroll 8
        for (int e = 0; e < NCH; e++) a += sA[t * LDSM + e] * s_bv[e];
        s_av[t] = a;
    }
    __syncthreads();

    // U = A * Wv -> sB  (tf32)
    chain_mm<false>(
        [&](int r, int k) { return sA[r * LDSM + k]; },
        [&](int n, int k) { return __ldg(&Wv[k * NCH + n]); },
        [&](int r, int c, float v0, float v1) {
            sB[r * LDSM + c] = v0; sB[r * LDSM + c + 1] = v1;
        }, wm, wn, grp, tq);
    __syncthreads();

    float gmv = __ldg(&gamma[0]);

    // M = gamma * Wo * U -> g_Mf (fragment-packed tf32)
    chain_mm<false>(
        [&](int r, int k) { return __ldg(&Wo[r * NCH + k]); },
        [&](int n, int k) { return sB[k * LDSM + n]; },
        [&](int r, int c, float v0, float v1) {
            g_Mf[b * 16384 + mf_index(r, c)]     = f2tf32(gmv * v0);
            g_Mf[b * 16384 + mf_index(r, c + 1)] = f2tf32(gmv * v1);
        }, wm, wn, grp, tq);

    // cvec = gamma * (Wo av + bo)
    if (t < NCH) {
        float a = 0.f;
        #pragma unroll 8
        for (int h = 0; h < NCH; h++) a += __ldg(&Wo[t * NCH + h]) * s_av[h];
        g_cvec[b * NCH + t] = gmv * (a + bo[t]);
    }
}

// ---------------------------------------------------------------------------
// Output: out = M * X + c 1^T + X
// R7 structure (quad-buffered X in smem, residual from smem, A-frags via
// LDG.128 from fragment-packed g_Mf) + software-pipelined A-frag prefetch:
// kt = 4s+ks is globally linear, so kt+1's fragments are loaded during kt's
// mma block. Only kt=0's L2 latency is exposed (hidden by stage-0 wait).
// ---------------------------------------------------------------------------
__global__ __launch_bounds__(256, 2) void k_out(const float* __restrict__ x,
                                                float* __restrict__ out) {
    extern __shared__ float sx[];   // 4 stages x 32 x XST = 69632 B
    int b = blockIdx.y;
    int tok0 = blockIdx.x * TOKT;
    int t = threadIdx.x;
    int lane = t & 31, wid = t >> 5;
    int grp = lane >> 2, tq = lane & 3;
    int wm = wid & 3, wn = wid >> 2;   // wn in {0,1}

    const float* xb = x + (size_t)b * NCH * NTOK;
    const uint4* Mf = (const uint4*)g_Mf + (size_t)b * 4096;

    int lrow = t >> 3, loff = (t & 7) << 4;   // 32 rows x 128 floats
    const float* gsrc = xb + (size_t)lrow * NTOK + tok0 + loff;
    #pragma unroll
    for (int s = 0; s < 4; s++) {
        uint32_t sd = (uint32_t)__cvta_generic_to_shared(sx + s * 32 * XST + lrow * XST + loff);
        const float* p = gsrc + (size_t)s * 32 * NTOK;
        #pragma unroll
        for (int j = 0; j < 4; j++) cpa16(sd + j * 16, p + j * 4);
        asm volatile("cp.async.commit_group;");
    }

    // prefetch A-frags for kt = 0 (overlaps the stage-0 cp.async wait)
    uint4 nav0 = __ldg(&Mf[(0 * 8 + wm * 2 + 0) * 32 + lane]);
    uint4 nav1 = __ldg(&Mf[(0 * 8 + wm * 2 + 1) * 32 + lane]);

    float acc[2][8][4];
    #pragma unroll
    for (int i = 0; i < 2; i++)
        #pragma unroll
        for (int j = 0; j < 8; j++)
            #pragma unroll
            for (int k = 0; k < 4; k++) acc[i][j][k] = 0.f;

    #pragma unroll
    for (int s = 0; s < 4; s++) {
        if (s == 0)      asm volatile("cp.async.wait_group 3;");
        else if (s == 1) asm volatile("cp.async.wait_group 2;");
        else if (s == 2) asm volatile("cp.async.wait_group 1;");
        else             asm volatile("cp.async.wait_group 0;");
        __syncthreads();
        const float* cur = sx + s * 32 * XST;

        #pragma unroll
        for (int ks = 0; ks < 4; ks++) {
            int kk = ks * 8;
            int kt = s * 4 + ks;
            uint4 av0 = nav0, av1 = nav1;
            if (kt < 15) {   // prefetch next kt's fragments
                nav0 = __ldg(&Mf[((kt + 1) * 8 + wm * 2 + 0) * 32 + lane]);
                nav1 = __ldg(&Mf[((kt + 1) * 8 + wm * 2 + 1) * 32 + lane]);
            }
            uint32_t a0[4] = {av0.x, av0.y, av0.z, av0.w};
            uint32_t a1[4] = {av1.x, av1.y, av1.z, av1.w};
            #pragma unroll
            for (int nt = 0; nt < 8; nt++) {
                int n0 = wn * 64 + nt * 8;
                uint32_t b0 = f2tf32(cur[(kk + tq) * XST + n0 + grp]);
                uint32_t b1 = f2tf32(cur[(kk + tq + 4) * XST + n0 + grp]);
                mma8(acc[0][nt], a0, b0, b1);
                mma8(acc[1][nt], a1, b0, b1);
            }
        }
    }

    float* ob = out + (size_t)b * NCH * NTOK;
    #pragma unroll
    for (int mt = 0; mt < 2; mt++) {
        int r  = wm * 32 + mt * 16 + grp;
        int r1 = r + 8;
        float cv0 = g_cvec[b * NCH + r];
        float cv1 = g_cvec[b * NCH + r1];
        const float* res0 = sx + (r >> 5) * 32 * XST + (r & 31) * XST;
        const float* res1 = sx + (r1 >> 5) * 32 * XST + (r1 & 31) * XST;
        #pragma unroll
        for (int nt = 0; nt < 8; nt++) {
            int cl = wn * 64 + nt * 8 + tq * 2;
            int c = tok0 + cl;
            size_t i0 = (size_t)r * NTOK + c;
            size_t i1 = (size_t)r1 * NTOK + c;
            ob[i0]     = acc[mt][nt][0] + cv0 + res0[cl];
            ob[i0 + 1] = acc[mt][nt][1] + cv0 + res0[cl + 1];
            ob[i1]     = acc[mt][nt][2] + cv1 + res1[cl];
            ob[i1 + 1] = acc[mt][nt][3] + cv1 + res1[cl + 1];
        }
    }
}

extern "C" void kernel_launch(void* const* d_in, const int* in_sizes, int n_in,
                              void* d_out, int out_size) {
    const float* x  = (const float*)d_in[0];
    const float* Wq = (const float*)d_in[1];
    const float* bq = (const float*)d_in[2];
    const float* Wk = (const float*)d_in[3];
    const float* bk = (const float*)d_in[4];
    const float* Wv = (const float*)d_in[5];
    const float* bv = (const float*)d_in[6];
    const float* Wo = (const float*)d_in[7];
    const float* bo = (const float*)d_in[8];
    const float* gm = (const float*)d_in[9];
    float* out = (float*)d_out;

    const int gram_smem  = 3 * NCH * GSTR * (int)sizeof(float);          // 104448
    const int chain_smem = 2 * NCH * LDSM * (int)sizeof(float);          // 135168
    const int out_smem   = 4 * 32 * XST * (int)sizeof(float);            // 69632
    cudaFuncSetAttribute(k_gram,  cudaFuncAttributeMaxDynamicSharedMemorySize, gram_smem);
    cudaFuncSetAttribute(k_chain, cudaFuncAttributeMaxDynamicSharedMemorySize, chain_smem);
    cudaFuncSetAttribute(k_out,   cudaFuncAttributeMaxDynamicSharedMemorySize, out_smem);

    k_gram<<<dim3(NCHUNK, NBAT), 256, gram_smem>>>(x);
    k_gred<<<(NBAT * NCH * NCH) / 256, 256>>>();
    k_chain<<<NBAT, 256, chain_smem>>>(Wq, bq, Wk, bk, Wv, bv, Wo, bo, gm);
    k_out<<<dim3(NTOK / TOKT, NBAT), 256, out_smem>>>(x, out);
}

// round 11
// speedup vs baseline: 1.1358x; 1.0607x over previous
#include <cuda_runtime.h>
#include <cstdint>
#include <cstddef>

// Channel self-attention via Gram restructuring:
//   G_b = X X^T, s_b = X 1
//   E = Wq G Wk^T + (Wq s) bk^T + bq (Wk s)^T + N bq bk^T ; A = softmax(E)
//   M = gamma * Wo (A Wv) ; c = gamma * (Wo A bv + bo)
//   out = M X + c 1^T + X
//
// Inner GEMM loops feed raw fp32 bits to tf32 mma (HW truncates mantissa,
// CUTLASS-default behavior) — no cvt instructions on the hot path. The
// precision-critical E-path (logits ~1e3) keeps explicit tf32x2 rna splits.

#define NTOK 36864
#define NCH 128
#define NBAT 8
#define NCHUNK 36
#define CHUNK 1024
#define GW 64     /* gram stage width (cols) */
#define GSTR 68   /* gram smem stride; 68%32==4 -> conflict-free */
#define LDSM 132
#define TOKT 128
#define XST 136   /* X stage stride; 136%32==8 -> conflict-free B frags */

__device__ float g_Gpart[NCHUNK * NBAT * NCH * NCH];
__device__ float g_spart[NCHUNK * NBAT * NCH];
__device__ float g_G[NBAT * NCH * NCH];
__device__ float g_s[NBAT * NCH];
__device__ uint32_t g_Mf[NBAT * 16384];   // M in tf32, mma-fragment-packed
__device__ float g_cvec[NBAT * NCH];

__device__ __forceinline__ uint32_t f2tf32(float f) {
    uint32_t u;
    asm("cvt.rna.tf32.f32 %0, %1;" : "=r"(u) : "f"(f));
    return u;
}

__device__ __forceinline__ void tf32split(float f, uint32_t& hi, uint32_t& lo) {
    uint32_t h;
    asm("cvt.rna.tf32.f32 %0, %1;" : "=r"(h) : "f"(f));
    float fh = __uint_as_float(h);
    float r = f - fh;
    uint32_t l;
    asm("cvt.rna.tf32.f32 %0, %1;" : "=r"(l) : "f"(r));
    hi = h; lo = l;
}

__device__ __forceinline__ void mma8(float* d, const uint32_t* a, uint32_t b0, uint32_t b1) {
    asm volatile(
        "mma.sync.aligned.m16n8k8.row.col.f32.tf32.tf32.f32 "
        "{%0,%1,%2,%3},{%4,%5,%6,%7},{%8,%9},{%0,%1,%2,%3};"
        : "+f"(d[0]), "+f"(d[1]), "+f"(d[2]), "+f"(d[3])
        : "r"(a[0]), "r"(a[1]), "r"(a[2]), "r"(a[3]), "r"(b0), "r"(b1));
}

__device__ __forceinline__ void cpa16(uint32_t dst, const void* src) {
    asm volatile("cp.async.cg.shared.global [%0],[%1],16;" :: "r"(dst), "l"(src));
}

// Fragment-packed M index: element (r, c) of the 128x128 matrix ->
// [kt(16)][mtile(8)][lane(32)][q(4)], lane = 4*grp+tq, q = qhi*2+qlo.
__device__ __forceinline__ int mf_index(int r, int c) {
    int kt = c >> 3, w = c & 7, qhi = w >> 2, tq = w & 3;
    int mtile = r >> 4, rr = r & 15, qlo = rr >> 3, grp = rr & 7;
    return ((kt * 8 + mtile) * 32 + grp * 4 + tq) * 4 + qhi * 2 + qlo;
}

// ---------------------------------------------------------------------------
// Gram: per (chunk, batch) block computes 128x128 partial X X^T over 1024 cols
// (16 stages of 64, double-buffered). Raw fp32 operands (HW tf32 truncation).
// Deterministic. 2 CTAs/SM.
// ---------------------------------------------------------------------------
__global__ __launch_bounds__(256, 2) void k_gram(const float* __restrict__ x) {
    extern __shared__ float sb[];   // 2 x 128 x GSTR = 69632 B
    int b = blockIdx.y, ch = blockIdx.x;
    int t = threadIdx.x;
    int lrow = t >> 1, lcol = (t & 1) << 5;
    int lane = t & 31, wid = t >> 5;
    int grp = lane >> 2, tq = lane & 3;
    int wm = wid & 3, wn = wid >> 2;

    const float* gsrc = x + (size_t)b * NCH * NTOK + (size_t)lrow * NTOK
                          + (size_t)ch * CHUNK + lcol;
    uint32_t sd0 = (uint32_t)__cvta_generic_to_shared(sb + lrow * GSTR + lcol);
    uint32_t sd1 = (uint32_t)__cvta_generic_to_shared(sb + NCH * GSTR + lrow * GSTR + lcol);

    float acc[2][8][4];
    #pragma unroll
    for (int i = 0; i < 2; i++)
        #pragma unroll
        for (int j = 0; j < 8; j++)
            #pragma unroll
            for (int k = 0; k < 4; k++) acc[i][j][k] = 0.f;
    float rsum = 0.f;

    #pragma unroll
    for (int j = 0; j < 8; j++) cpa16(sd0 + j * 16, gsrc + j * 4);
    asm volatile("cp.async.commit_group;");

    const int NST = CHUNK / GW;  // 16
    for (int s = 0; s < NST; s++) {
        if (s + 1 < NST) {
            uint32_t dd = ((s + 1) & 1) ? sd1 : sd0;
            const float* p = gsrc + (s + 1) * GW;
            #pragma unroll
            for (int j = 0; j < 8; j++) cpa16(dd + j * 16, p + j * 4);
            asm volatile("cp.async.commit_group;");
            asm volatile("cp.async.wait_group 1;");
        } else {
            asm volatile("cp.async.wait_group 0;");
        }
        __syncthreads();
        const float* cur = sb + (s & 1) * NCH * GSTR;
        const uint32_t* curu = (const uint32_t*)cur;

        {
            const float4* rp4 = (const float4*)(cur + lrow * GSTR + lcol);
            #pragma unroll
            for (int i = 0; i < 8; i++) {
                float4 v = rp4[i];
                rsum += v.x + v.y + v.z + v.w;
            }
        }

        #pragma unroll
        for (int ks = 0; ks < 8; ks++) {
            int kk = ks * 8;
            uint32_t a[2][4];
            #pragma unroll
            for (int mt = 0; mt < 2; mt++) {
                int r0 = wm * 32 + mt * 16;
                a[mt][0] = curu[(r0 + grp) * GSTR + kk + tq];
                a[mt][1] = curu[(r0 + grp + 8) * GSTR + kk + tq];
                a[mt][2] = curu[(r0 + grp) * GSTR + kk + tq + 4];
                a[mt][3] = curu[(r0 + grp + 8) * GSTR + kk + tq + 4];
            }
            #pragma unroll
            for (int nt = 0; nt < 8; nt++) {
                int n0 = wn * 64 + nt * 8;
                uint32_t b0 = curu[(n0 + grp) * GSTR + kk + tq];
                uint32_t b1 = curu[(n0 + grp) * GSTR + kk + tq + 4];
                mma8(acc[0][nt], a[0], b0, b1);
                mma8(acc[1][nt], a[1], b0, b1);
            }
        }
        __syncthreads();
    }

    float* gp = g_Gpart + ((size_t)ch * NBAT + b) * NCH * NCH;
    #pragma unroll
    for (int mt = 0; mt < 2; mt++) {
        #pragma unroll
        for (int nt = 0; nt < 8; nt++) {
            int r = wm * 32 + mt * 16 + grp;
            int c = wn * 64 + nt * 8 + tq * 2;
            gp[r * NCH + c]           = acc[mt][nt][0];
            gp[r * NCH + c + 1]       = acc[mt][nt][1];
            gp[(r + 8) * NCH + c]     = acc[mt][nt][2];
            gp[(r + 8) * NCH + c + 1] = acc[mt][nt][3];
        }
    }
    rsum += __shfl_xor_sync(0xffffffffu, rsum, 1);
    if ((t & 1) == 0) g_spart[(ch * NBAT + b) * NCH + lrow] = rsum;
}

__global__ void k_gred() {
    int j = blockIdx.x * 256 + threadIdx.x;
    float a = 0.f;
    #pragma unroll
    for (int ch = 0; ch < NCHUNK; ch++) a += g_Gpart[(size_t)ch * (NBAT * NCH * NCH) + j];
    g_G[j] = a;
    if (j < NBAT * NCH) {
        float t2 = 0.f;
        #pragma unroll
        for (int ch = 0; ch < NCHUNK; ch++) t2 += g_spart[ch * (NBAT * NCH) + j];
        g_s[j] = t2;
    }
}

// ---------------------------------------------------------------------------
// Fused small chain: one block per batch, all 128x128 matmuls via MMA in smem.
// ---------------------------------------------------------------------------
template<bool X2, class FA, class FB, class FE>
__device__ __forceinline__ void chain_mm(FA fa, FB fb, FE fe,
                                         int wm, int wn, int grp, int tq) {
    float acc[2][8][4];
    #pragma unroll
    for (int i = 0; i < 2; i++)
        #pragma unroll
        for (int j = 0; j < 8; j++)
            #pragma unroll
            for (int k = 0; k < 4; k++) acc[i][j][k] = 0.f;

    for (int kk = 0; kk < NCH; kk += 8) {
        uint32_t ah[2][4], al[2][4];
        #pragma unroll
        for (int mt = 0; mt < 2; mt++) {
            int r0 = wm * 32 + mt * 16;
            #pragma unroll
            for (int q = 0; q < 4; q++) {
                int rr = r0 + grp + ((q & 1) ? 8 : 0);
                int kc = kk + tq + ((q >> 1) ? 4 : 0);
                float f = fa(rr, kc);
                if constexpr (X2) tf32split(f, ah[mt][q], al[mt][q]);
                else ah[mt][q] = f2tf32(f);
            }
        }
        #pragma unroll
        for (int nt = 0; nt < 8; nt++) {
            int n = wn * 64 + nt * 8 + grp;
            float g0 = fb(n, kk + tq);
            float g1 = fb(n, kk + tq + 4);
            uint32_t bh0, bh1, bl0, bl1;
            if constexpr (X2) { tf32split(g0, bh0, bl0); tf32split(g1, bh1, bl1); }
            else { bh0 = f2tf32(g0); bh1 = f2tf32(g1); }
            mma8(acc[0][nt], ah[0], bh0, bh1);
            mma8(acc[1][nt], ah[1], bh0, bh1);
            if constexpr (X2) {
                mma8(acc[0][nt], al[0], bh0, bh1);
                mma8(acc[1][nt], al[1], bh0, bh1);
                mma8(acc[0][nt], ah[0], bl0, bl1);
                mma8(acc[1][nt], ah[1], bl0, bl1);
            }
        }
    }
    #pragma unroll
    for (int mt = 0; mt < 2; mt++)
        #pragma unroll
        for (int nt = 0; nt < 8; nt++) {
            int r = wm * 32 + mt * 16 + grp;
            int c = wn * 64 + nt * 8 + tq * 2;
            fe(r, c, acc[mt][nt][0], acc[mt][nt][1]);
            fe(r + 8, c, acc[mt][nt][2], acc[mt][nt][3]);
        }
}

__global__ __launch_bounds__(256) void k_chain(
    const float* __restrict__ Wq, const float* __restrict__ bq,
    const float* __restrict__ Wk, const float* __restrict__ bk,
    const float* __restrict__ Wv, const float* __restrict__ bv,
    const float* __restrict__ Wo, const float* __restrict__ bo,
    const float* __restrict__ gamma) {
    extern __shared__ float sm[];
    float* sA = sm;                 // 128 x LDSM
    float* sB = sm + NCH * LDSM;    // 128 x LDSM
    __shared__ float s_s[NCH], s_qs[NCH], s_ks[NCH], s_av[NCH];
    __shared__ float s_bq[NCH], s_bk[NCH], s_bv[NCH];

    int b = blockIdx.x, t = threadIdx.x;
    int lane = t & 31, wid = t >> 5;
    int grp = lane >> 2, tq = lane & 3;
    int wm = wid & 3, wn = wid >> 2;

    if (t < NCH) {
        s_s[t] = g_s[b * NCH + t];
        s_bq[t] = bq[t]; s_bk[t] = bk[t]; s_bv[t] = bv[t];
    }
    __syncthreads();

    // qs = Wq s, ks = Wk s
    {
        int d = t & 127;
        const float* W = (t < NCH) ? Wq : Wk;
        float a = 0.f;
        #pragma unroll 8
        for (int c = 0; c < NCH; c++) a += __ldg(&W[d * NCH + c]) * s_s[c];
        if (t < NCH) s_qs[d] = a; else s_ks[d] = a;
    }

    // G -> sA
    for (int i = t; i < NCH * 32; i += 256) {
        int r = i >> 5, c = (i & 31) << 2;
        *(float4*)(sA + r * LDSM + c) =
            *(const float4*)(g_G + (size_t)b * NCH * NCH + r * NCH + c);
    }
    __syncthreads();

    // T1 = Wq * G -> sB   (tf32x2)
    chain_mm<true>(
        [&](int r, int k) { return __ldg(&Wq[r * NCH + k]); },
        [&](int n, int k) { return sA[k * LDSM + n]; },
        [&](int r, int c, float v0, float v1) {
            sB[r * LDSM + c] = v0; sB[r * LDSM + c + 1] = v1;
        }, wm, wn, grp, tq);
    __syncthreads();

    // E = T1 * Wk^T + rank-1 -> sA   (tf32x2)
    chain_mm<true>(
        [&](int r, int k) { return sB[r * LDSM + k]; },
        [&](int n, int k) { return __ldg(&Wk[n * NCH + k]); },
        [&](int r, int c, float v0, float v1) {
            sA[r * LDSM + c] = v0 + s_qs[r] * s_bk[c]
                             + s_bq[r] * (s_ks[c] + (float)NTOK * s_bk[c]);
            sA[r * LDSM + c + 1] = v1 + s_qs[r] * s_bk[c + 1]
                             + s_bq[r] * (s_ks[c + 1] + (float)NTOK * s_bk[c + 1]);
        }, wm, wn, grp, tq);
    __syncthreads();

    // softmax rows of sA
    for (int r = wid; r < NCH; r += 8) {
        float4 v = *(float4*)(sA + r * LDSM + lane * 4);
        float m = fmaxf(fmaxf(v.x, v.y), fmaxf(v.z, v.w));
        #pragma unroll
        for (int o = 16; o; o >>= 1) m = fmaxf(m, __shfl_xor_sync(0xffffffffu, m, o));
        float e0 = __expf(v.x - m), e1 = __expf(v.y - m);
        float e2 = __expf(v.z - m), e3 = __expf(v.w - m);
        float s2 = e0 + e1 + e2 + e3;
        #pragma unroll
        for (int o = 16; o; o >>= 1) s2 += __shfl_xor_sync(0xffffffffu, s2, o);
        float inv = 1.f / s2;
        v.x = e0 * inv; v.y = e1 * inv; v.z = e2 * inv; v.w = e3 * inv;
        *(float4*)(sA + r * LDSM + lane * 4) = v;
    }
    __syncthreads();

    // av = A * bv
    if (t < NCH) {
        float a = 0.f;
        #pragma unroll 8
        for (int e = 0; e < NCH; e++) a += sA[t * LDSM + e] * s_bv[e];
        s_av[t] = a;
    }
    __syncthreads();

    // U = A * Wv -> sB  (tf32)
    chain_mm<false>(
        [&](int r, int k) { return sA[r * LDSM + k]; },
        [&](int n, int k) { return __ldg(&Wv[k * NCH + n]); },
        [&](int r, int c, float v0, float v1) {
            sB[r * LDSM + c] = v0; sB[r * LDSM + c + 1] = v1;
        }, wm, wn, grp, tq);
    __syncthreads();

    float gmv = __ldg(&gamma[0]);

    // M = gamma * Wo * U -> g_Mf (fragment-packed tf32)
    chain_mm<false>(
        [&](int r, int k) { return __ldg(&Wo[r * NCH + k]); },
        [&](int n, int k) { return sB[k * LDSM + n]; },
        [&](int r, int c, float v0, float v1) {
            g_Mf[b * 16384 + mf_index(r, c)]     = f2tf32(gmv * v0);
            g_Mf[b * 16384 + mf_index(r, c + 1)] = f2tf32(gmv * v1);
        }, wm, wn, grp, tq);

    // cvec = gamma * (Wo av + bo)
    if (t < NCH) {
        float a = 0.f;
        #pragma unroll 8
        for (int h = 0; h < NCH; h++) a += __ldg(&Wo[t * NCH + h]) * s_av[h];
        g_cvec[b * NCH + t] = gmv * (a + bo[t]);
    }
}

// ---------------------------------------------------------------------------
// Output: out = M * X + c 1^T + X
// Quad-buffered X in smem, residual from smem, A-frags via pipelined LDG.128
// from fragment-packed g_Mf (kt+1 prefetched during kt's mma block). B-frags
// are raw fp32 bits (HW tf32 truncation) — no cvt on the hot path.
// ---------------------------------------------------------------------------
__global__ __launch_bounds__(256, 2) void k_out(const float* __restrict__ x,
                                                float* __restrict__ out) {
    extern __shared__ float sx[];   // 4 stages x 32 x XST = 69632 B
    int b = blockIdx.y;
    int tok0 = blockIdx.x * TOKT;
    int t = threadIdx.x;
    int lane = t & 31, wid = t >> 5;
    int grp = lane >> 2, tq = lane & 3;
    int wm = wid & 3, wn = wid >> 2;   // wn in {0,1}

    const float* xb = x + (size_t)b * NCH * NTOK;
    const uint4* Mf = (const uint4*)g_Mf + (size_t)b * 4096;

    int lrow = t >> 3, loff = (t & 7) << 4;   // 32 rows x 128 floats
    const float* gsrc = xb + (size_t)lrow * NTOK + tok0 + loff;
    #pragma unroll
    for (int s = 0; s < 4; s++) {
        uint32_t sd = (uint32_t)__cvta_generic_to_shared(sx + s * 32 * XST + lrow * XST + loff);
        const float* p = gsrc + (size_t)s * 32 * NTOK;
        #pragma unroll
        for (int j = 0; j < 4; j++) cpa16(sd + j * 16, p + j * 4);
        asm volatile("cp.async.commit_group;");
    }

    // prefetch A-frags for kt = 0 (overlaps the stage-0 cp.async wait)
    uint4 nav0 = __ldg(&Mf[(0 * 8 + wm * 2 + 0) * 32 + lane]);
    uint4 nav1 = __ldg(&Mf[(0 * 8 + wm * 2 + 1) * 32 + lane]);

    float acc[2][8][4];
    #pragma unroll
    for (int i = 0; i < 2; i++)
        #pragma unroll
        for (int j = 0; j < 8; j++)
            #pragma unroll
            for (int k = 0; k < 4; k++) acc[i][j][k] = 0.f;

    #pragma unroll
    for (int s = 0; s < 4; s++) {
        if (s == 0)      asm volatile("cp.async.wait_group 3;");
        else if (s == 1) asm volatile("cp.async.wait_group 2;");
        else if (s == 2) asm volatile("cp.async.wait_group 1;");
        else             asm volatile("cp.async.wait_group 0;");
        __syncthreads();
        const uint32_t* curu = (const uint32_t*)(sx + s * 32 * XST);

        #pragma unroll
        for (int ks = 0; ks < 4; ks++) {
            int kk = ks * 8;
            int kt = s * 4 + ks;
            uint4 av0 = nav0, av1 = nav1;
            if (kt < 15) {   // prefetch next kt's fragments
                nav0 = __ldg(&Mf[((kt + 1) * 8 + wm * 2 + 0) * 32 + lane]);
                nav1 = __ldg(&Mf[((kt + 1) * 8 + wm * 2 + 1) * 32 + lane]);
            }
            uint32_t a0[4] = {av0.x, av0.y, av0.z, av0.w};
            uint32_t a1[4] = {av1.x, av1.y, av1.z, av1.w};
            #pragma unroll
            for (int nt = 0; nt < 8; nt++) {
                int n0 = wn * 64 + nt * 8;
                uint32_t b0 = curu[(kk + tq) * XST + n0 + grp];
                uint32_t b1 = curu[(kk + tq + 4) * XST + n0 + grp];
                mma8(acc[0][nt], a0, b0, b1);
                mma8(acc[1][nt], a1, b0, b1);
            }
        }
    }

    float* ob = out + (size_t)b * NCH * NTOK;
    #pragma unroll
    for (int mt = 0; mt < 2; mt++) {
        int r  = wm * 32 + mt * 16 + grp;
        int r1 = r + 8;
        float cv0 = g_cvec[b * NCH + r];
        float cv1 = g_cvec[b * NCH + r1];
        const float* res0 = sx + (r >> 5) * 32 * XST + (r & 31) * XST;
        const float* res1 = sx + (r1 >> 5) * 32 * XST + (r1 & 31) * XST;
        #pragma unroll
        for (int nt = 0; nt < 8; nt++) {
            int cl = wn * 64 + nt * 8 + tq * 2;
            int c = tok0 + cl;
            size_t i0 = (size_t)r * NTOK + c;
            size_t i1 = (size_t)r1 * NTOK + c;
            ob[i0]     = acc[mt][nt][0] + cv0 + res0[cl];
            ob[i0 + 1] = acc[mt][nt][1] + cv0 + res0[cl + 1];
            ob[i1]     = acc[mt][nt][2] + cv1 + res1[cl];
            ob[i1 + 1] = acc[mt][nt][3] + cv1 + res1[cl + 1];
        }
    }
}

extern "C" void kernel_launch(void* const* d_in, const int* in_sizes, int n_in,
                              void* d_out, int out_size) {
    const float* x  = (const float*)d_in[0];
    const float* Wq = (const float*)d_in[1];
    const float* bq = (const float*)d_in[2];
    const float* Wk = (const float*)d_in[3];
    const float* bk = (const float*)d_in[4];
    const float* Wv = (const float*)d_in[5];
    const float* bv = (const float*)d_in[6];
    const float* Wo = (const float*)d_in[7];
    const float* bo = (const float*)d_in[8];
    const float* gm = (const float*)d_in[9];
    float* out = (float*)d_out;

    const int gram_smem  = 2 * NCH * GSTR * (int)sizeof(float);          // 69632
    const int chain_smem = 2 * NCH * LDSM * (int)sizeof(float);          // 135168
    const int out_smem   = 4 * 32 * XST * (int)sizeof(float);            // 69632
    cudaFuncSetAttribute(k_gram,  cudaFuncAttributeMaxDynamicSharedMemorySize, gram_smem);
    cudaFuncSetAttribute(k_chain, cudaFuncAttributeMaxDynamicSharedMemorySize, chain_smem);
    cudaFuncSetAttribute(k_out,   cudaFuncAttributeMaxDynamicSharedMemorySize, out_smem);

    k_gram<<<dim3(NCHUNK, NBAT), 256, gram_smem>>>(x);
    k_gred<<<(NBAT * NCH * NCH) / 256, 256>>>();
    k_chain<<<NBAT, 256, chain_smem>>>(Wq, bq, Wk, bk, Wv, bv, Wo, bo, gm);
    k_out<<<dim3(NTOK / TOKT, NBAT), 256, out_smem>>>(x, out);
}